// round 10
// baseline (speedup 1.0000x reference)
#include <cuda_runtime.h>
#include <cuda_fp16.h>
#include <stdint.h>

#define N_NODES  50000
#define N_EDGES  1600000
#define IN_F     128
#define OUT_F    128
#define HEADS    4
#define HEAD_DIM 32
#define NEG_SLOPE 0.2f

#define GEMM_BM     64
#define GEMM_BLOCKS 782             // ceil(50000/64)
#define SCAT_BLOCKS 3125            // 1.6M edges / (128 thr * 4 edges)

// ---------------- device scratch ----------------
__device__ __half2 g_h2[N_NODES * (OUT_F / 2)];  // h as half2 (12.8 MB)
__device__ float   g_as[N_NODES * HEADS];
__device__ float   g_ad[N_NODES * HEADS];
__device__ uint4   g_Wf[2048];                   // W in mma B-fragment layout (32KB)
__device__ int     g_cnt[N_NODES];
__device__ int     g_off[N_NODES + 1];
__device__ int     g_cur[N_NODES];
__device__ int     g_srcs[N_EDGES];
__device__ int     g_is64;

// ---------------- init: dtype detect + W fragment packing ----------------
// g_Wf[(ks*8 + j)*32 + lane] = uint4{ b0(n=2j), b1(n=2j), b0(n=2j+1), b1(n=2j+1) }
// where for m16n8k16.col B frag: b0 = half2(Wt[k0][col], Wt[k0+1][col]),
// b1 = half2(Wt[k0+8][col], Wt[k0+9][col]); col = n*8 + lane/4,
// k0 = ks*16 + (lane%4)*2; Wt[k][c] = W[c*IN_F + k].
__global__ __launch_bounds__(256) void init_kernel(
    const int* __restrict__ ei, const float* __restrict__ W)
{
    const int L = blockIdx.x * 256 + threadIdx.x;   // 8 blocks * 256 = 2048
    const int lane = L & 31;
    const int j    = (L >> 5) & 7;
    const int ks   = L >> 8;
    const int k0   = ks * 16 + (lane & 3) * 2;

    uint4 q;
    #pragma unroll
    for (int p = 0; p < 2; p++) {
        const int col = (2 * j + p) * 8 + (lane >> 2);
        const float* wr = W + col * IN_F;
        __half2 b0 = __floats2half2_rn(wr[k0],     wr[k0 + 1]);
        __half2 b1 = __floats2half2_rn(wr[k0 + 8], wr[k0 + 9]);
        if (p == 0) { q.x = *(const unsigned*)&b0; q.y = *(const unsigned*)&b1; }
        else        { q.z = *(const unsigned*)&b0; q.w = *(const unsigned*)&b1; }
    }
    g_Wf[L] = q;

    if (L == 0) {
        int allzero = 1;
        #pragma unroll 1
        for (int i2 = 1; i2 < 256; i2 += 2)
            if (ei[i2] != 0) { allzero = 0; break; }
        g_is64 = allzero;
    }
}

// ---------------- histogram of dst (4 edges/thread) -----------------------
__global__ __launch_bounds__(256) void hist_kernel(const int* __restrict__ ei32) {
    const int e4 = (blockIdx.x * blockDim.x + threadIdx.x) * 4;
    if (e4 >= N_EDGES) return;
    int d0, d1, d2, d3;
    if (g_is64) {
        const longlong2* p = (const longlong2*)((const long long*)ei32 + N_EDGES + e4);
        longlong2 a = p[0], b = p[1];
        d0 = (int)a.x; d1 = (int)a.y; d2 = (int)b.x; d3 = (int)b.y;
    } else {
        int4 d = *(const int4*)(ei32 + N_EDGES + e4);
        d0 = d.x; d1 = d.y; d2 = d.z; d3 = d.w;
    }
    atomicAdd(&g_cnt[d0], 1);
    atomicAdd(&g_cnt[d1], 1);
    atomicAdd(&g_cnt[d2], 1);
    atomicAdd(&g_cnt[d3], 1);
}

// ---------------- single-CTA scan, coalesced 1024-rounds ------------------
__global__ __launch_bounds__(1024) void scan_kernel() {
    __shared__ int wtot[32];
    const int t = threadIdx.x;
    const int lane = t & 31, wid = t >> 5;
    const unsigned m = 0xffffffffu;
    int base = 0;

    #pragma unroll 1
    for (int i = 0; i < (N_NODES + 1023) / 1024; i++) {
        const int idx = i * 1024 + t;
        const int v = (idx < N_NODES) ? g_cnt[idx] : 0;
        int incl = v;
        #pragma unroll
        for (int off = 1; off < 32; off <<= 1) {
            int u = __shfl_up_sync(m, incl, off);
            if (lane >= off) incl += u;
        }
        if (lane == 31) wtot[wid] = incl;
        __syncthreads();
        if (wid == 0) {
            int w2 = wtot[lane];
            #pragma unroll
            for (int off = 1; off < 32; off <<= 1) {
                int u = __shfl_up_sync(m, w2, off);
                if (lane >= off) w2 += u;
            }
            wtot[lane] = w2;
        }
        __syncthreads();
        const int excl = incl - v + (wid ? wtot[wid - 1] : 0) + base;
        if (idx < N_NODES) { g_off[idx] = excl; g_cur[idx] = excl; }
        base += wtot[31];
        __syncthreads();
    }
    if (t == 0) g_off[N_NODES] = base;
}

// ---------------- fused tensor-core GEMM || scatter ------------------------
// GEMM blocks: 128 thr = 4 warps; CTA = 64 rows x 128 cols.
// Warp w: rows rowbase + w*16 + {lane/4, lane/4+8}; 16 n-tiles of 8 cols.
__device__ __forceinline__ void mma16816(
    float* c, unsigned a0, unsigned a1, unsigned a2, unsigned a3,
    unsigned b0, unsigned b1)
{
    asm volatile(
        "mma.sync.aligned.m16n8k16.row.col.f32.f16.f16.f32 "
        "{%0,%1,%2,%3}, {%4,%5,%6,%7}, {%8,%9}, {%0,%1,%2,%3};"
        : "+f"(c[0]), "+f"(c[1]), "+f"(c[2]), "+f"(c[3])
        : "r"(a0), "r"(a1), "r"(a2), "r"(a3), "r"(b0), "r"(b1));
}

__global__ __launch_bounds__(128) void gemm_scatter_kernel(
    const float* __restrict__ x,
    const int*   __restrict__ ei32,
    const float* __restrict__ a)
{
    __shared__ __half xh[GEMM_BM][IN_F + 8];

    if (blockIdx.x >= GEMM_BLOCKS) {
        // ---- scatter path: 4 edges per thread ----
        const int e = (blockIdx.x - GEMM_BLOCKS) * 512 + threadIdx.x * 4;
        int s[4], d[4];
        if (g_is64) {
            const long long* ei = (const long long*)ei32;
            const longlong2* sp = (const longlong2*)(ei + e);
            const longlong2* dp = (const longlong2*)(ei + N_EDGES + e);
            longlong2 s01 = sp[0], s23 = sp[1], d01 = dp[0], d23 = dp[1];
            s[0] = (int)s01.x; s[1] = (int)s01.y; s[2] = (int)s23.x; s[3] = (int)s23.y;
            d[0] = (int)d01.x; d[1] = (int)d01.y; d[2] = (int)d23.x; d[3] = (int)d23.y;
        } else {
            int4 sv = *(const int4*)(ei32 + e);
            int4 dv = *(const int4*)(ei32 + N_EDGES + e);
            s[0] = sv.x; s[1] = sv.y; s[2] = sv.z; s[3] = sv.w;
            d[0] = dv.x; d[1] = dv.y; d[2] = dv.z; d[3] = dv.w;
        }
        #pragma unroll
        for (int p = 0; p < 4; p++) {
            int pos = atomicAdd(&g_cur[d[p]], 1);
            g_srcs[pos] = s[p];
        }
        return;
    }

    // ---- GEMM path ----
    const int t    = threadIdx.x;
    const int lane = t & 31;
    const int w    = t >> 5;
    const int rowbase = blockIdx.x * GEMM_BM;

    // stage x tile as half (coalesced float4 reads)
    for (int f4 = t; f4 < GEMM_BM * 32; f4 += 128) {
        const int row = f4 >> 5, c4 = f4 & 31;
        const int grow = rowbase + row;
        float4 v = make_float4(0.f, 0.f, 0.f, 0.f);
        if (grow < N_NODES) v = *(const float4*)(x + (size_t)grow * IN_F + c4 * 4);
        __half2 h0 = __floats2half2_rn(v.x, v.y);
        __half2 h1 = __floats2half2_rn(v.z, v.w);
        uint2 u;
        u.x = *(const unsigned*)&h0;
        u.y = *(const unsigned*)&h1;
        *(uint2*)&xh[row][c4 * 4] = u;
    }
    __syncthreads();

    float acc[16][4];
    #pragma unroll
    for (int n = 0; n < 16; n++)
        #pragma unroll
        for (int q = 0; q < 4; q++) acc[n][q] = 0.f;

    const int sr = w * 16 + (lane >> 2);
    const int cc = (lane & 3) * 2;

    #pragma unroll
    for (int ks = 0; ks < 8; ks++) {
        const int kb = ks * 16;
        const unsigned a0 = *(const unsigned*)&xh[sr][kb + cc];
        const unsigned a1 = *(const unsigned*)&xh[sr + 8][kb + cc];
        const unsigned a2 = *(const unsigned*)&xh[sr][kb + cc + 8];
        const unsigned a3 = *(const unsigned*)&xh[sr + 8][kb + cc + 8];
        #pragma unroll
        for (int j = 0; j < 8; j++) {
            const uint4 q = g_Wf[(ks * 8 + j) * 32 + lane];
            mma16816(acc[2 * j],     a0, a1, a2, a3, q.x, q.y);
            mma16816(acc[2 * j + 1], a0, a1, a2, a3, q.z, q.w);
        }
    }

    // epilogue: h -> half2 store + fused alpha reductions
    const int cq = lane & 3;
    const unsigned msk = 0xffffffffu;

    #pragma unroll
    for (int rh = 0; rh < 2; rh++) {
        const int row = rowbase + w * 16 + (lane >> 2) + rh * 8;
        const bool valid = (row < N_NODES);
        float ps[4] = {0.f, 0.f, 0.f, 0.f};
        float pd[4] = {0.f, 0.f, 0.f, 0.f};

        #pragma unroll
        for (int n = 0; n < 16; n++) {
            const float c0 = acc[n][rh * 2];
            const float c1 = acc[n][rh * 2 + 1];
            if (valid) {
                __half2 hp = __floats2half2_rn(c0, c1);
                ((unsigned*)g_h2)[(size_t)row * 64 + n * 4 + cq] = *(const unsigned*)&hp;
            }
            const int head = n >> 2;
            const int wc   = (n & 3) * 8 + cq * 2;        // within-head col
            const float2 asv = *(const float2*)&a[head * 64 + wc];
            const float2 adv = *(const float2*)&a[head * 64 + 32 + wc];
            ps[head] += c0 * asv.x + c1 * asv.y;
            pd[head] += c0 * adv.x + c1 * adv.y;
        }
        #pragma unroll
        for (int h = 0; h < 4; h++) {
            ps[h] += __shfl_xor_sync(msk, ps[h], 1);
            ps[h] += __shfl_xor_sync(msk, ps[h], 2);
            pd[h] += __shfl_xor_sync(msk, pd[h], 1);
            pd[h] += __shfl_xor_sync(msk, pd[h], 2);
        }
        if (valid) {
            g_as[row * HEADS + cq] = ps[cq];   // lane cq of the quad owns head cq
            g_ad[row * HEADS + cq] = pd[cq];
        }
    }
}

// ---------------- gather: warp per node, half-warp per edge ---------------
__device__ __forceinline__ float leaky(float v) {
    return (v > 0.f) ? v : NEG_SLOPE * v;
}

__global__ __launch_bounds__(256) void gather_kernel(float* __restrict__ out) {
    const int n = blockIdx.x * 8 + (threadIdx.x >> 5);
    if (n >= N_NODES) return;
    const int lane = threadIdx.x & 31;
    const int hw = lane >> 4;
    const int sl = lane & 15;
    const int h  = sl >> 2;
    const float myad = g_ad[n * HEADS + h];

    float acc[8];
    #pragma unroll
    for (int j = 0; j < 8; j++) acc[j] = 0.f;

    const int start = g_off[n];
    const int end   = g_off[n + 1];
    int e = start;

    #pragma unroll 1
    for (; e + 4 <= end; e += 4) {
        #pragma unroll
        for (int p = 0; p < 2; p++) {
            const int s = g_srcs[e + 2 * p + hw];
            const float att = leaky(g_as[s * HEADS + h] + myad);
            const uint4 u = *(const uint4*)&g_h2[(size_t)s * 64 + sl * 4];
            float2 f;
            f = __half22float2(*(const __half2*)&u.x);
            acc[0] = fmaf(att, f.x, acc[0]); acc[1] = fmaf(att, f.y, acc[1]);
            f = __half22float2(*(const __half2*)&u.y);
            acc[2] = fmaf(att, f.x, acc[2]); acc[3] = fmaf(att, f.y, acc[3]);
            f = __half22float2(*(const __half2*)&u.z);
            acc[4] = fmaf(att, f.x, acc[4]); acc[5] = fmaf(att, f.y, acc[5]);
            f = __half22float2(*(const __half2*)&u.w);
            acc[6] = fmaf(att, f.x, acc[6]); acc[7] = fmaf(att, f.y, acc[7]);
        }
    }
    #pragma unroll 1
    for (; e < end; e += 2) {
        if (e + hw < end) {
            const int s = g_srcs[e + hw];
            const float att = leaky(g_as[s * HEADS + h] + myad);
            const uint4 u = *(const uint4*)&g_h2[(size_t)s * 64 + sl * 4];
            float2 f;
            f = __half22float2(*(const __half2*)&u.x);
            acc[0] = fmaf(att, f.x, acc[0]); acc[1] = fmaf(att, f.y, acc[1]);
            f = __half22float2(*(const __half2*)&u.y);
            acc[2] = fmaf(att, f.x, acc[2]); acc[3] = fmaf(att, f.y, acc[3]);
            f = __half22float2(*(const __half2*)&u.z);
            acc[4] = fmaf(att, f.x, acc[4]); acc[5] = fmaf(att, f.y, acc[5]);
            f = __half22float2(*(const __half2*)&u.w);
            acc[6] = fmaf(att, f.x, acc[6]); acc[7] = fmaf(att, f.y, acc[7]);
        }
    }

    const unsigned msk = 0xffffffffu;
    #pragma unroll
    for (int j = 0; j < 8; j++)
        acc[j] += __shfl_xor_sync(msk, acc[j], 16);

    float* op = out + (size_t)n * OUT_F + sl * 8;
    if (hw == 0)
        *(float4*)op = make_float4(acc[0], acc[1], acc[2], acc[3]);
    else
        *(float4*)(op + 4) = make_float4(acc[4], acc[5], acc[6], acc[7]);
}

// ---------------- launch -------------------------------------------------
extern "C" void kernel_launch(void* const* d_in, const int* in_sizes, int n_in,
                              void* d_out, int out_size) {
    const float* x  = (const float*)d_in[0];
    const int*   ei = (const int*)d_in[1];
    const float* W  = (const float*)d_in[2];
    const float* a  = (const float*)d_in[3];
    float* out = (float*)d_out;

    void* cntp = nullptr;
    cudaGetSymbolAddress(&cntp, g_cnt);
    cudaMemsetAsync(cntp, 0, N_NODES * sizeof(int));

    init_kernel<<<8, 256>>>(ei, W);
    hist_kernel<<<(N_EDGES / 4 + 255) / 256, 256>>>(ei);
    scan_kernel<<<1, 1024>>>();
    gemm_scatter_kernel<<<GEMM_BLOCKS + SCAT_BLOCKS, 128>>>(x, ei, a);
    gather_kernel<<<(N_NODES + 7) / 8, 256>>>(out);
}